// round 2
// baseline (speedup 1.0000x reference)
#include <cuda_runtime.h>

// Problem constants
namespace {
constexpr int BATCH   = 32;
constexpr int CIN     = 512;
constexpr int PIX     = 56 * 56;   // 3136
constexpr int NWIN    = 8;         // OUTPUT_CHANNEL / OUTPUT_UNIT_DIM
constexpr int WSTRIDE = 32;
constexpr int KD      = 64;        // INPUT_UNIT_DIM
constexpr int OD      = 64;        // OUTPUT_UNIT_DIM
constexpr int TP      = 64;        // pixels per CTA tile
constexpr int NTILES  = PIX / TP;  // 49
}

// Pre-transposed weights: g_wT[k*64 + o] = w[o*64 + k]
__device__ float g_wT[KD * OD];

__global__ void transpose_w_kernel(const float* __restrict__ w) {
    int t = threadIdx.x;
#pragma unroll
    for (int i = 0; i < 16; i++) {
        int idx = i * 256 + t;       // 0..4095
        int k = idx >> 6;
        int o = idx & 63;
        g_wT[idx] = w[o * KD + k];
    }
}

// ---- packed f32x2 helpers (Blackwell fma.rn.f32x2) ----
__device__ __forceinline__ unsigned long long pack2(float a, float b) {
    unsigned long long r;
    asm("mov.b64 %0, {%1, %2};" : "=l"(r) : "f"(a), "f"(b));
    return r;
}
__device__ __forceinline__ void ffma2(unsigned long long& d,
                                      unsigned long long a,
                                      unsigned long long b) {
    asm("fma.rn.f32x2 %0, %1, %2, %0;" : "+l"(d) : "l"(a), "l"(b));
}
__device__ __forceinline__ float2 unpack2(unsigned long long v) {
    float2 f;
    asm("mov.b64 {%0, %1}, %2;" : "=f"(f.x), "=f"(f.y) : "l"(v));
    return f;
}

// One CTA: computes out[b, o*8+n, tile*64 .. +64) for all o in [0,64)
// from x[b, n*32 + k, same pixels], k in [0,64).
__global__ __launch_bounds__(256, 4)
void win_gemm_kernel(const float* __restrict__ x, float* __restrict__ out) {
    __shared__ float sx[KD * TP];    // [k][px]  (px contiguous)
    __shared__ float swT[KD * OD];   // [k][o]   (o contiguous)

    const int t    = threadIdx.x;
    const int tx   = t & 15;   // pixel group: 4 pixels each
    const int ty   = t >> 4;   // output group: 4 outputs each
    const int tile = blockIdx.x;
    const int n    = blockIdx.y;
    const int b    = blockIdx.z;

    // --- load x tile: 64 channels x 64 pixels, fully coalesced float4 ---
    const float* xbase = x + ((long)b * CIN + n * WSTRIDE) * PIX + tile * TP;
#pragma unroll
    for (int i = 0; i < 4; i++) {
        int idx4 = i * 256 + t;           // 0..1023 float4 slots
        int ch   = idx4 >> 4;             // 16 float4 per 64-px row
        int pos  = (idx4 & 15) << 2;
        *(float4*)(sx + ch * TP + pos) =
            *(const float4*)(xbase + (long)ch * PIX + pos);
    }
    // --- load pre-transposed weights: coalesced, conflict-free ---
#pragma unroll
    for (int i = 0; i < 4; i++) {
        int off = (i * 256 + t) << 2;     // 0..4095 floats in float4 steps
        *(float4*)(swT + off) = *(const float4*)(g_wT + off);
    }
    __syncthreads();

    // accumulators: 4 outputs x 4 pixels = 8 packed f32x2
    unsigned long long acc[4][2];
#pragma unroll
    for (int j = 0; j < 4; j++) { acc[j][0] = 0ull; acc[j][1] = 0ull; }

    const float* xs = sx + 4 * tx;
    const float* ws = swT + 4 * ty;

#pragma unroll 8
    for (int k = 0; k < KD; k++) {
        // 4 pixels as two packed f32x2 (16B-aligned LDS.128)
        ulonglong2 xv = *(const ulonglong2*)(xs + k * TP);
        // 4 consecutive outputs' weights for this k (LDS.128, broadcast)
        float4 wv = *(const float4*)(ws + k * OD);
        unsigned long long w0 = pack2(wv.x, wv.x);
        unsigned long long w1 = pack2(wv.y, wv.y);
        unsigned long long w2 = pack2(wv.z, wv.z);
        unsigned long long w3 = pack2(wv.w, wv.w);
        ffma2(acc[0][0], xv.x, w0); ffma2(acc[0][1], xv.y, w0);
        ffma2(acc[1][0], xv.x, w1); ffma2(acc[1][1], xv.y, w1);
        ffma2(acc[2][0], xv.x, w2); ffma2(acc[2][1], xv.y, w2);
        ffma2(acc[3][0], xv.x, w3); ffma2(acc[3][1], xv.y, w3);
    }

    // --- epilogue: out channel = o*NWIN + n, 4 contiguous pixels -> STG.128 ---
#pragma unroll
    for (int j = 0; j < 4; j++) {
        int o = 4 * ty + j;
        float2 lo = unpack2(acc[j][0]);
        float2 hi = unpack2(acc[j][1]);
        float4 r  = make_float4(lo.x, lo.y, hi.x, hi.y);
        *(float4*)(out + ((long)b * CIN + o * NWIN + n) * PIX + tile * TP + 4 * tx) = r;
    }
}

extern "C" void kernel_launch(void* const* d_in, const int* in_sizes, int n_in,
                              void* d_out, int out_size) {
    const float* x = (const float*)d_in[0];   // (32, 512, 56, 56) fp32
    const float* w = (const float*)d_in[1];   // (64, 64) fp32
    float* out = (float*)d_out;               // (32, 512, 56, 56) fp32

    transpose_w_kernel<<<1, 256>>>(w);
    dim3 grid(NTILES, NWIN, BATCH);
    win_gemm_kernel<<<grid, 256>>>(x, out);
}

// round 4
// speedup vs baseline: 1.8677x; 1.8677x over previous
#include <cuda_runtime.h>
#include <cuda_bf16.h>
#include <cstdint>

#define DINLINE __device__ __forceinline__

namespace {
constexpr int CIN = 512, PIX = 3136, NWIN = 8, WSTRIDE = 32;
constexpr int TM = 128;      // pixels per CTA tile (MMA M)
constexpr int NTILES = 25;   // ceil(3136/128), last tile has 64 valid px
// static smem byte offsets: x_hi, x_lo [128 rows x 128B]; w_hi, w_lo [64 rows x 128B]
constexpr int SM_XH = 0;
constexpr int SM_XL = 16384;
constexpr int SM_WH = 32768;
constexpr int SM_WL = 40960;
constexpr int SM_TOTAL = 49152;  // 48KB static
}

// W split into bf16 hi/lo, stored as the row-swizzled smem image:
// element (o,k) -> byte off = o*128 + ((k*2) ^ ((o&7)<<4))
__device__ __align__(16) unsigned short g_wh[4096];
__device__ __align__(16) unsigned short g_wl[4096];

__global__ void prep_w(const float* __restrict__ w) {
    int t = threadIdx.x;
#pragma unroll
    for (int i = 0; i < 16; i++) {
        int e = i * 256 + t;           // e = o*64 + k
        int o = e >> 6, k = e & 63;
        float f = w[e];
        __nv_bfloat16 hb = __float2bfloat16(f);
        float hf = __bfloat162float(hb);
        __nv_bfloat16 lb = __float2bfloat16(f - hf);
        uint32_t idx = (uint32_t)(o * 128 + ((k * 2) ^ ((o & 7) << 4))) >> 1;
        g_wh[idx] = __bfloat16_as_ushort(hb);
        g_wl[idx] = __bfloat16_as_ushort(lb);
    }
}

// ---- PTX helpers ----
DINLINE uint32_t smem_u32(const void* p) {
    uint32_t a;
    asm("{ .reg .u64 t; cvta.to.shared.u64 t, %1; cvt.u32.u64 %0, t; }" : "=r"(a) : "l"(p));
    return a;
}
// pack {hi16 = bf16(a_hi), lo16 = bf16(a_lo)}
DINLINE uint32_t cvt2(float a_hi, float a_lo) {
    uint32_t r;
    asm("cvt.rn.bf16x2.f32 %0, %1, %2;" : "=r"(r) : "f"(a_hi), "f"(a_lo));
    return r;
}
DINLINE void ldsm4(uint32_t* r, uint32_t a) {
    asm volatile("ldmatrix.sync.aligned.m8n8.x4.shared.b16 {%0,%1,%2,%3}, [%4];"
                 : "=r"(r[0]), "=r"(r[1]), "=r"(r[2]), "=r"(r[3]) : "r"(a));
}
DINLINE void mma_bf16(float* c, const uint32_t* a, uint32_t b0, uint32_t b1) {
    asm volatile(
        "mma.sync.aligned.m16n8k16.row.col.f32.bf16.bf16.f32 "
        "{%0,%1,%2,%3}, {%4,%5,%6,%7}, {%8,%9}, {%0,%1,%2,%3};"
        : "+f"(c[0]), "+f"(c[1]), "+f"(c[2]), "+f"(c[3])
        : "r"(a[0]), "r"(a[1]), "r"(a[2]), "r"(a[3]), "r"(b0), "r"(b1));
}

__global__ void __launch_bounds__(256)
win_mma(const float* __restrict__ x, float* __restrict__ out) {
    __shared__ __align__(16) char smem[SM_TOTAL];
    const uint32_t sb = smem_u32(smem);
    const int t = threadIdx.x;
    const int lane = t & 31, w = t >> 5;
    const int tile = blockIdx.x, nwin = blockIdx.y, b = blockIdx.z;

    // ---- copy pre-swizzled weight images (8KB hi + 8KB lo) ----
    {
        const uint4* wh = (const uint4*)g_wh;
        const uint4* wl = (const uint4*)g_wl;
        uint4* dh = (uint4*)(smem + SM_WH);
        uint4* dl = (uint4*)(smem + SM_WL);
        dh[t] = wh[t];  dh[t + 256] = wh[t + 256];
        dl[t] = wl[t];  dl[t + 256] = wl[t + 256];
    }

    // ---- load x tile [64 k][128 px], convert bf16 hi/lo, store [px][k] swizzled ----
    {
        const int pl = t & 127;            // pixel row (A row)
        const int kh = (t >> 7) * 32;      // k half
        int p = tile * TM + pl;
        if (p >= PIX) p = PIX - 1;         // tail clamp; rows guarded at epilogue
        const float* xp = x + ((size_t)(b * CIN + nwin * WSTRIDE + kh)) * PIX + p;
#pragma unroll
        for (int c = 0; c < 4; c++) {      // chunks of 8 k
            float v[8];
#pragma unroll
            for (int j = 0; j < 8; j++) v[j] = xp[(size_t)(c * 8 + j) * PIX];
            uint32_t h[4], l[4];
#pragma unroll
            for (int j = 0; j < 4; j++) {
                uint32_t hp = cvt2(v[2 * j + 1], v[2 * j]);
                float he = __uint_as_float(hp << 16);         // bf16(v_even) as f32
                float ho = __uint_as_float(hp & 0xFFFF0000u); // bf16(v_odd)  as f32
                h[j] = hp;
                l[j] = cvt2(v[2 * j + 1] - ho, v[2 * j] - he);
            }
            uint32_t off = (uint32_t)(pl * 128 + ((kh * 2 + c * 16) ^ ((pl & 7) << 4)));
            *(uint4*)(smem + SM_XH + off) = make_uint4(h[0], h[1], h[2], h[3]);
            *(uint4*)(smem + SM_XL + off) = make_uint4(l[0], l[1], l[2], l[3]);
        }
    }
    __syncthreads();

    // ---- register-fragment MMA: warp w owns px rows [w*16, w*16+16) ----
    float acc[8][4];
#pragma unroll
    for (int j = 0; j < 8; j++)
#pragma unroll
        for (int i = 0; i < 4; i++) acc[j][i] = 0.0f;

    // A ldmatrix lane address pieces
    const int rA = (w << 4) + ((lane >> 3) & 1) * 8 + (lane & 7);
    const int cA = (lane >> 4) * 16;
    // B ldmatrix lane address pieces
    const int rB = ((lane >> 4) & 1) * 8 + (lane & 7);
    const int cB = ((lane >> 3) & 1) * 16;

#pragma unroll
    for (int ks = 0; ks < 4; ks++) {
        uint32_t ah[4], al[4];
        uint32_t ca = (uint32_t)((ks * 32 + cA) ^ ((rA & 7) << 4));
        uint32_t aH = sb + SM_XH + rA * 128 + ca;
        ldsm4(ah, aH);
        ldsm4(al, aH + (SM_XL - SM_XH));

        uint32_t cb = (uint32_t)((ks * 32 + cB) ^ ((rB & 7) << 4));
#pragma unroll
        for (int jn2 = 0; jn2 < 4; jn2++) {
            uint32_t bh[4], bl[4];
            uint32_t bH = sb + SM_WH + (rB + jn2 * 16) * 128 + cb;
            ldsm4(bh, bH);
            ldsm4(bl, bH + (SM_WL - SM_WH));
            // n-step 2*jn2 uses (r0,r1); n-step 2*jn2+1 uses (r2,r3)
            mma_bf16(acc[2 * jn2],     ah, bh[0], bh[1]);
            mma_bf16(acc[2 * jn2],     al, bh[0], bh[1]);
            mma_bf16(acc[2 * jn2],     ah, bl[0], bl[1]);
            mma_bf16(acc[2 * jn2 + 1], ah, bh[2], bh[3]);
            mma_bf16(acc[2 * jn2 + 1], al, bh[2], bh[3]);
            mma_bf16(acc[2 * jn2 + 1], ah, bl[2], bl[3]);
        }
    }

    // ---- epilogue: direct STG (full 32B sectors along px) ----
    {
        const int grp = lane >> 2, tid4 = lane & 3;
        const int px0 = tile * TM + (w << 4) + grp;
        const bool v0 = px0 < PIX, v1 = (px0 + 8) < PIX;
        float* ob = out + ((size_t)(b * CIN + nwin)) * PIX;
#pragma unroll
        for (int j = 0; j < 8; j++) {
            int o = j * 8 + tid4 * 2;
            size_t s0 = (size_t)(o * NWIN) * PIX;
            size_t s1 = (size_t)((o + 1) * NWIN) * PIX;
            if (v0) { ob[s0 + px0] = acc[j][0]; ob[s1 + px0] = acc[j][1]; }
            if (v1) { ob[s0 + px0 + 8] = acc[j][2]; ob[s1 + px0 + 8] = acc[j][3]; }
        }
    }
}

extern "C" void kernel_launch(void* const* d_in, const int* in_sizes, int n_in,
                              void* d_out, int out_size) {
    const float* x = (const float*)d_in[0];   // (32, 512, 56, 56) fp32
    const float* w = (const float*)d_in[1];   // (64, 64) fp32
    float* out = (float*)d_out;               // (32, 512, 56, 56) fp32

    prep_w<<<1, 256>>>(w);
    dim3 grid(NTILES, NWIN, 32);
    win_mma<<<grid, 256>>>(x, out);
}